// round 2
// baseline (speedup 1.0000x reference)
#include <cuda_runtime.h>
#include <math.h>

#define NGR    256
#define NPG_   256
#define FDIM   128
#define EPG    4096
#define DLAT   97
#define KTOP   30
#define C1_    16
#define C2_    32
#define T2_    11
#define DENSE_ 352
#define NT     512

// shared layout (float units)
// h1 0, h2 8192, h3 16384, g 24576, z4 32768, invd 33024,
// Ws 33280 (4224, pitch-132 transposed for L0 / k*32+lane for L1,2),
// bs 37504 (32), scratch 37536 (8192),
// ints: offs @45728 (257), cnt (256), elist (4096)
#define SM_FLOATS 50337
static const int SMEM_BYTES = SM_FLOATS * 4;

__global__ __launch_bounds__(NT, 1)
void dgcnn_kernel(const float* __restrict__ nf,
                  const int* __restrict__ src, const int* __restrict__ dst,
                  const int* __restrict__ degs,
                  const float* __restrict__ W0, const float* __restrict__ b0,
                  const float* __restrict__ W1, const float* __restrict__ b1,
                  const float* __restrict__ W2, const float* __restrict__ b2,
                  const float* __restrict__ W3, const float* __restrict__ b3,
                  const float* __restrict__ c1w, const float* __restrict__ c1b,
                  const float* __restrict__ c2w, const float* __restrict__ c2b,
                  const float* __restrict__ ow, const float* __restrict__ ob,
                  float* __restrict__ out)
{
    extern __shared__ float sm[];
    float* h1      = sm;
    float* h2      = h1 + 8192;
    float* h3      = h2 + 8192;
    float* g       = h3 + 8192;
    float* z4      = g  + 8192;
    float* invd    = z4 + 256;
    float* Ws      = invd + 256;        // 4224
    float* bs      = Ws + 4224;         // 32
    float* scratch = bs + 32;           // 8192
    int*   offs    = (int*)(scratch + 8192);   // 257
    int*   cnt     = offs + 257;               // 256
    int*   elist   = cnt + 256;                // 4096 (stores ls*32)

    const int b    = blockIdx.x;
    const int t    = threadIdx.x;
    const int w    = t >> 5;
    const int lane = t & 31;
    const int base = b * NPG_;

    // ---- degrees ----
    if (t < 256) {
        int d = degs[base + t];
        cnt[t]  = d;
        invd[t] = 1.0f / ((float)d + 1.0f);
    }
    // ---- W0 staged transposed with pitch 132: Ws[l*132 + k] = W0[k*32+l] ----
    for (int i = t; i < FDIM * 32; i += NT) {
        int k = i >> 5, l = i & 31;
        Ws[l * 132 + k] = W0[i];
    }
    if (t < 32) bs[t] = b0[t];
    __syncthreads();

    // ---- parallel exclusive scan of degrees -> offs ----
    if (t < 256) offs[t] = cnt[t];
    __syncthreads();
#pragma unroll
    for (int d = 1; d < 256; d <<= 1) {
        int u = (t < 256 && t >= d) ? offs[t - d] : 0;
        __syncthreads();
        if (t < 256) offs[t] += u;
        __syncthreads();
    }
    int exc = 0;
    if (t < 256) exc = offs[t] - cnt[t];
    __syncthreads();
    if (t < 256) { offs[t] = exc; cnt[t] = exc; }
    if (t == 0) offs[256] = EPG;
    __syncthreads();

    // ---- build CSR of in-edges, store src offsets (ls*32) ----
    for (int i = t; i < EPG; i += NT) {
        int e  = b * EPG + i;
        int ls = src[e] - base;
        int ld = dst[e] - base;
        int pos = atomicAdd(&cnt[ld], 1);
        elist[pos] = ls << 5;
    }
    __syncthreads();

    // ---- Layer 0 GEMM: g = nf @ W0 (chunks of 64 nodes, warp=4 nodes) ----
    for (int chunk = 0; chunk < 4; chunk++) {
        const float4* s4 = (const float4*)(nf + (size_t)(base + chunk * 64) * FDIM);
        float4* d4 = (float4*)scratch;
        for (int i = t; i < 64 * FDIM / 4; i += NT) d4[i] = s4[i];
        __syncthreads();

        float acc[4] = {0.f, 0.f, 0.f, 0.f};
        const float* wbase = Ws + lane * 132;
#pragma unroll
        for (int k0 = 0; k0 < FDIM; k0 += 8) {
            float4 wa = *(const float4*)(wbase + k0);
            float4 wb = *(const float4*)(wbase + k0 + 4);
#pragma unroll
            for (int i = 0; i < 4; i++) {
                const float4* r = (const float4*)(scratch + (w * 4 + i) * FDIM + k0);
                float4 ra = r[0], rb = r[1];
                acc[i] = fmaf(ra.x, wa.x, acc[i]);
                acc[i] = fmaf(ra.y, wa.y, acc[i]);
                acc[i] = fmaf(ra.z, wa.z, acc[i]);
                acc[i] = fmaf(ra.w, wa.w, acc[i]);
                acc[i] = fmaf(rb.x, wb.x, acc[i]);
                acc[i] = fmaf(rb.y, wb.y, acc[i]);
                acc[i] = fmaf(rb.z, wb.z, acc[i]);
                acc[i] = fmaf(rb.w, wb.w, acc[i]);
            }
        }
#pragma unroll
        for (int i = 0; i < 4; i++)
            g[(chunk * 64 + w * 4 + i) * 32 + lane] = acc[i];
        __syncthreads();
    }

    // ---- Layer 0 aggregate + tanh -> h1 (warp = 16 nodes) ----
#pragma unroll 1
    for (int nn = 0; nn < 16; nn++) {
        int n = w * 16 + nn;
        float acc = g[n * 32 + lane];
        int beg = offs[n], end = offs[n + 1];
        int j = beg;
        for (; j + 3 < end; j += 4) {
            int o0 = elist[j], o1 = elist[j + 1], o2 = elist[j + 2], o3 = elist[j + 3];
            float v0 = g[o0 + lane], v1 = g[o1 + lane];
            float v2 = g[o2 + lane], v3 = g[o3 + lane];
            acc += (v0 + v1) + (v2 + v3);
        }
        for (; j < end; j++) acc += g[elist[j] + lane];
        h1[n * 32 + lane] = tanhf((acc + bs[lane]) * invd[n]);
    }
    __syncthreads();

    // ---- Layers 1,2 (32->32) ----
    {
        const float* Wg[2] = {W1, W2};
        const float* bg[2] = {b1, b2};
        float* hin = h1;
        float* houts[2] = {h2, h3};
        for (int L = 0; L < 2; L++) {
            for (int i = t; i < 1024; i += NT) Ws[i] = Wg[L][i];
            if (t < 32) bs[t] = bg[L][t];
            __syncthreads();

            float wr[32];
#pragma unroll
            for (int k = 0; k < 32; k++) wr[k] = Ws[k * 32 + lane];
#pragma unroll 1
            for (int nn = 0; nn < 16; nn++) {
                int n = w * 16 + nn;
                const float* row = hin + n * 32;
                float acc = 0.f;
#pragma unroll
                for (int k = 0; k < 32; k += 4) {
                    float4 r4 = *(const float4*)(row + k);
                    acc = fmaf(r4.x, wr[k],     acc);
                    acc = fmaf(r4.y, wr[k + 1], acc);
                    acc = fmaf(r4.z, wr[k + 2], acc);
                    acc = fmaf(r4.w, wr[k + 3], acc);
                }
                g[n * 32 + lane] = acc;
            }
            __syncthreads();

            float* hout = houts[L];
#pragma unroll 1
            for (int nn = 0; nn < 16; nn++) {
                int n = w * 16 + nn;
                float acc = g[n * 32 + lane];
                int beg = offs[n], end = offs[n + 1];
                int j = beg;
                for (; j + 3 < end; j += 4) {
                    int o0 = elist[j], o1 = elist[j + 1], o2 = elist[j + 2], o3 = elist[j + 3];
                    float v0 = g[o0 + lane], v1 = g[o1 + lane];
                    float v2 = g[o2 + lane], v3 = g[o3 + lane];
                    acc += (v0 + v1) + (v2 + v3);
                }
                for (; j < end; j++) acc += g[elist[j] + lane];
                hout[n * 32 + lane] = tanhf((acc + bs[lane]) * invd[n]);
            }
            __syncthreads();
            hin = hout;
        }
    }

    // ---- Layer 3 (32->1) -> z4 ----
    {
        float* g1 = scratch;
        float w3r = W3[lane];
        float b3v = b3[0];
#pragma unroll 1
        for (int nn = 0; nn < 16; nn++) {
            int n = w * 16 + nn;
            float v = h3[n * 32 + lane] * w3r;
#pragma unroll
            for (int off = 16; off; off >>= 1)
                v += __shfl_xor_sync(0xffffffffu, v, off);
            if (lane == 0) g1[n] = v;
        }
        __syncthreads();
        if (t < 256) {
            float acc = g1[t];
            int beg = offs[t], end = offs[t + 1];
            int j = beg;
            for (; j + 3 < end; j += 4) {
                float v0 = g1[elist[j] >> 5],     v1 = g1[elist[j + 1] >> 5];
                float v2 = g1[elist[j + 2] >> 5], v3 = g1[elist[j + 3] >> 5];
                acc += (v0 + v1) + (v2 + v3);
            }
            for (; j < end; j++) acc += g1[elist[j] >> 5];
            z4[t] = tanhf((acc + b3v) * invd[t]);
        }
        __syncthreads();
    }

    // ---- sortpool rank selection ----
    int* selrow = cnt;
    if (t < 256) {
        float v = z4[t];
        int r = 0;
        for (int j = 0; j < 256; j++) {
            float u = z4[j];
            r += (int)((u > v) || (u == v && j < t));
        }
        if (r < KTOP) selrow[r] = t;
    }
    __syncthreads();

    // ---- gather sp[30][97] ----
    float* sp = scratch;
    for (int i = t; i < KTOP * DLAT; i += NT) {
        int k = i / DLAT, d = i - k * DLAT;
        int n = selrow[k];
        float v;
        if (d < 32)      v = h1[n * 32 + d];
        else if (d < 64) v = h2[n * 32 + d - 32];
        else if (d < 96) v = h3[n * 32 + d - 64];
        else             v = z4[n];
        sp[i] = v;
    }
    __syncthreads();

    // ---- conv1 (stride D) + relu -> out1[16][30] ----
    float* out1 = scratch + 3000;
    if (t < C1_ * KTOP) {
        int c = t & 15, k = t >> 4;
        float acc = c1b[c];
        const float* wr = c1w + c * DLAT;
        const float* sr = sp + k * DLAT;
        for (int d = 0; d < DLAT; d++) acc = fmaf(sr[d], wr[d], acc);
        out1[c * KTOP + k] = fmaxf(acc, 0.f);
    }
    __syncthreads();

    // ---- maxpool(2,2) -> pool[16][15] ----
    float* pool = scratch + 3500;
    if (t < C1_ * 15) {
        int c = t / 15, tt = t - c * 15;
        pool[t] = fmaxf(out1[c * KTOP + 2 * tt], out1[c * KTOP + 2 * tt + 1]);
    }
    __syncthreads();

    // ---- conv2 (kw=5) + relu -> out2[32][11] ----
    float* out2 = scratch + 3800;
    if (t < C2_ * T2_) {
        int c2 = t / T2_, tt = t - c2 * T2_;
        float acc = c2b[c2];
#pragma unroll
        for (int c1 = 0; c1 < C1_; c1++) {
            const float* wv = c2w + (c2 * C1_ + c1) * 5;
            const float* pv = pool + c1 * 15 + tt;
#pragma unroll
            for (int j = 0; j < 5; j++) acc = fmaf(pv[j], wv[j], acc);
        }
        out2[t] = fmaxf(acc, 0.f);
    }
    __syncthreads();

    // ---- dense + relu ----
    if (w == 0) {
        float a0 = 0.f, a1 = 0.f;
        for (int i = lane; i < DENSE_; i += 32) {
            float x = out2[i];
            a0 = fmaf(x, ow[i * 2 + 0], a0);
            a1 = fmaf(x, ow[i * 2 + 1], a1);
        }
#pragma unroll
        for (int off = 16; off; off >>= 1) {
            a0 += __shfl_xor_sync(0xffffffffu, a0, off);
            a1 += __shfl_xor_sync(0xffffffffu, a1, off);
        }
        if (lane == 0) {
            out[b * 2 + 0] = fmaxf(a0 + ob[0], 0.f);
            out[b * 2 + 1] = fmaxf(a1 + ob[1], 0.f);
        }
    }
}

extern "C" void kernel_launch(void* const* d_in, const int* in_sizes, int n_in,
                              void* d_out, int out_size)
{
    int iSrc, iDst, iDeg, iW0, ib0, iW1, ib1, iW2, ib2, iW3, ib3;
    int ic1w, ic1b, ic2w, ic2b, iow, iob;
    if (n_in > 1 && in_sizes[1] == NGR * EPG) {
        iSrc = 1; iDst = 2; iDeg = 3;
        iW0 = 4;  ib0 = 5;  iW1 = 6;  ib1 = 7;
        iW2 = 8;  ib2 = 9;  iW3 = 10; ib3 = 11;
        ic1w = 12; ic1b = 13; ic2w = 14; ic2b = 15; iow = 16; iob = 17;
    } else {
        iW0 = 1;  ib0 = 2;  iW1 = 3;  ib1 = 4;
        iW2 = 5;  ib2 = 6;  iW3 = 7;  ib3 = 8;
        ic1w = 9; ic1b = 10; ic2w = 11; ic2b = 12; iow = 13; iob = 14;
        iSrc = 15; iDst = 16; iDeg = 17;
    }

    cudaFuncSetAttribute(dgcnn_kernel,
                         cudaFuncAttributeMaxDynamicSharedMemorySize, SMEM_BYTES);

    dgcnn_kernel<<<NGR, NT, SMEM_BYTES>>>(
        (const float*)d_in[0],
        (const int*)d_in[iSrc], (const int*)d_in[iDst], (const int*)d_in[iDeg],
        (const float*)d_in[iW0], (const float*)d_in[ib0],
        (const float*)d_in[iW1], (const float*)d_in[ib1],
        (const float*)d_in[iW2], (const float*)d_in[ib2],
        (const float*)d_in[iW3], (const float*)d_in[ib3],
        (const float*)d_in[ic1w], (const float*)d_in[ic1b],
        (const float*)d_in[ic2w], (const float*)d_in[ic2b],
        (const float*)d_in[iow], (const float*)d_in[iob],
        (float*)d_out);
}

// round 5
// speedup vs baseline: 1.5199x; 1.5199x over previous
#include <cuda_runtime.h>
#include <math.h>

#define NGR    256
#define NPG_   256
#define FDIM   128
#define EPG    4096
#define DLAT   97
#define KTOP   30
#define C1_    16
#define C2_    32
#define T2_    11
#define DENSE_ 352
#define NT     256

// shared layout (float units), all float4-aligned where needed
#define OFF_H1    0        // 8192
#define OFF_H2    8192     // 8192
#define OFF_H3    16384    // 8192
#define OFF_G     24576    // 8224  (257 rows x 32, row 256 = zeros)
#define OFF_Z4    32800    // 256
#define OFF_INVD  33056    // 256
#define OFF_WS0   33312    // 4224  (transposed pitch-132)
#define OFF_WS1   37536    // 1024
#define OFF_WS2   38560    // 1024
#define OFF_BS    39584    // 96 (b0,b1,b2)
#define OFF_SCR   39680    // 8192
#define OFF_OFFS  47872    // 257 ints
#define OFF_CNT   48129    // 256 ints
#define OFF_ELIST 48388    // 5120 ints (16B aligned)
#define SM_FLOATS (48388 + 5120)
static const int SMEM_BYTES = SM_FLOATS * 4;

__global__ __launch_bounds__(NT, 1)
void dgcnn_kernel(const float* __restrict__ nf,
                  const int* __restrict__ src, const int* __restrict__ dst,
                  const int* __restrict__ degs,
                  const float* __restrict__ W0, const float* __restrict__ b0,
                  const float* __restrict__ W1, const float* __restrict__ b1,
                  const float* __restrict__ W2, const float* __restrict__ b2,
                  const float* __restrict__ W3, const float* __restrict__ b3,
                  const float* __restrict__ c1w, const float* __restrict__ c1b,
                  const float* __restrict__ c2w, const float* __restrict__ c2b,
                  const float* __restrict__ ow, const float* __restrict__ ob,
                  float* __restrict__ out)
{
    extern __shared__ float sm[];
    float* h1    = sm + OFF_H1;
    float* h2    = sm + OFF_H2;
    float* h3    = sm + OFF_H3;
    float* g     = sm + OFF_G;
    float* z4    = sm + OFF_Z4;
    float* invd  = sm + OFF_INVD;
    float* Ws0   = sm + OFF_WS0;
    float* Ws1   = sm + OFF_WS1;
    float* Ws2   = sm + OFF_WS2;
    float* bs    = sm + OFF_BS;       // bs, bs+32, bs+64
    float* scr   = sm + OFF_SCR;
    int*   offs  = (int*)(sm + OFF_OFFS);
    int*   cnt   = (int*)(sm + OFF_CNT);
    int*   elist = (int*)(sm + OFF_ELIST);

    const int b    = blockIdx.x;
    const int t    = threadIdx.x;
    const int w    = t >> 5;
    const int lane = t & 31;
    const int base = b * NPG_;

    // ---- init: degrees (padded to x4), zero row 256 of g, stage all weights ----
    int pdeg;
    {
        int d = degs[base + t];
        pdeg = (d + 3) & ~3;
        invd[t] = 1.0f / ((float)d + 1.0f);
        cnt[t] = d;               // true degree, needed for padding fill
        g[256 * 32 + lane] = 0.f; // every warp writes the zero row (idempotent)
    }
    // W0 transposed with pitch 132: Ws0[l*132 + k] = W0[k*32+l]
    for (int i = t; i < FDIM * 32; i += NT) {
        int k = i >> 5, l = i & 31;
        Ws0[l * 132 + k] = W0[i];
    }
    for (int i = t; i < 1024; i += NT) { Ws1[i] = W1[i]; Ws2[i] = W2[i]; }
    if (t < 32) { bs[t] = b0[t]; bs[32 + t] = b1[t]; bs[64 + t] = b2[t]; }

    // ---- Hillis-Steele inclusive scan of padded degrees -> offs (exclusive) ----
    offs[t] = pdeg;
    __syncthreads();
#pragma unroll
    for (int d = 1; d < 256; d <<= 1) {
        int u = (t >= d) ? offs[t - d] : 0;
        __syncthreads();
        offs[t] += u;
        __syncthreads();
    }
    int inc = offs[t];
    int exc = inc - pdeg;
    __syncthreads();
    offs[t] = exc;
    if (t == 255) offs[256] = inc;
    __syncthreads();
    int fill_beg = exc + cnt[t];   // after true edges
    int fill_end = offs[t + 1];
    cnt[t] = exc;
    __syncthreads();

    // ---- build CSR of in-edges (values are ls*32), then pad with dummy 256*32 ----
    for (int i = t; i < EPG; i += NT) {
        int e  = b * EPG + i;
        int ls = src[e] - base;
        int ld = dst[e] - base;
        int pos = atomicAdd(&cnt[ld], 1);
        elist[pos] = ls << 5;
    }
    __syncthreads();
    for (int p = fill_beg; p < fill_end; p++) elist[p] = 256 << 5;
    __syncthreads();

    // ---- Layer 0 GEMM: g = nf @ W0 (4 chunks of 64 nodes; warp: 8 nodes) ----
    for (int chunk = 0; chunk < 4; chunk++) {
        const float4* s4 = (const float4*)(nf + (size_t)(base + chunk * 64) * FDIM);
        float4* d4 = (float4*)scr;
        for (int i = t; i < 64 * FDIM / 4; i += NT) d4[i] = s4[i];
        __syncthreads();

        float acc[8] = {0.f,0.f,0.f,0.f,0.f,0.f,0.f,0.f};
        const float* wbase = Ws0 + lane * 132;
#pragma unroll 4
        for (int k0 = 0; k0 < FDIM; k0 += 4) {
            float4 wv = *(const float4*)(wbase + k0);
#pragma unroll
            for (int i = 0; i < 8; i++) {
                float4 r = *(const float4*)(scr + (w * 8 + i) * FDIM + k0);
                acc[i] = fmaf(r.x, wv.x, acc[i]);
                acc[i] = fmaf(r.y, wv.y, acc[i]);
                acc[i] = fmaf(r.z, wv.z, acc[i]);
                acc[i] = fmaf(r.w, wv.w, acc[i]);
            }
        }
#pragma unroll
        for (int i = 0; i < 8; i++)
            g[(chunk * 64 + w * 8 + i) * 32 + lane] = acc[i];
        __syncthreads();
    }

    // ---- Layer 0 aggregate + tanh -> h1 (warp: 32 nodes) ----
#pragma unroll 1
    for (int nn = 0; nn < 32; nn++) {
        int n = w * 32 + nn;
        float acc = g[n * 32 + lane];
        int beg = offs[n], end = offs[n + 1];
        for (int j = beg; j < end; j += 4) {
            int4 e4 = *(const int4*)(elist + j);
            float v0 = g[e4.x + lane], v1 = g[e4.y + lane];
            float v2 = g[e4.z + lane], v3 = g[e4.w + lane];
            acc += (v0 + v1) + (v2 + v3);
        }
        h1[n * 32 + lane] = tanhf((acc + bs[lane]) * invd[n]);
    }
    __syncthreads();

    // ---- Layers 1,2 (32->32) ----
    {
        float* hin = h1;
        for (int L = 0; L < 2; L++) {
            const float* Wst = (L == 0) ? Ws1 : Ws2;
            float bv = bs[32 + L * 32 + lane];
            float* hout = (L == 0) ? h2 : h3;

            float wr[32];
#pragma unroll
            for (int k = 0; k < 32; k++) wr[k] = Wst[k * 32 + lane];
#pragma unroll 1
            for (int nn = 0; nn < 32; nn++) {
                int n = w * 32 + nn;
                const float* row = hin + n * 32;
                float acc = 0.f;
#pragma unroll
                for (int k = 0; k < 32; k += 4) {
                    float4 r4 = *(const float4*)(row + k);
                    acc = fmaf(r4.x, wr[k],     acc);
                    acc = fmaf(r4.y, wr[k + 1], acc);
                    acc = fmaf(r4.z, wr[k + 2], acc);
                    acc = fmaf(r4.w, wr[k + 3], acc);
                }
                g[n * 32 + lane] = acc;
            }
            __syncthreads();

#pragma unroll 1
            for (int nn = 0; nn < 32; nn++) {
                int n = w * 32 + nn;
                float acc = g[n * 32 + lane];
                int beg = offs[n], end = offs[n + 1];
                for (int j = beg; j < end; j += 4) {
                    int4 e4 = *(const int4*)(elist + j);
                    float v0 = g[e4.x + lane], v1 = g[e4.y + lane];
                    float v2 = g[e4.z + lane], v3 = g[e4.w + lane];
                    acc += (v0 + v1) + (v2 + v3);
                }
                hout[n * 32 + lane] = tanhf((acc + bv) * invd[n]);
            }
            __syncthreads();
            hin = hout;
        }
    }

    // ---- Layer 3 (32->1) -> z4 ----
    {
        float* g1 = scr;                 // 257 entries, [256] = 0 dummy
        float w3r = W3[lane];
        float b3v = b3[0];
        if (t == 0) g1[256] = 0.f;
#pragma unroll 1
        for (int nn = 0; nn < 32; nn++) {
            int n = w * 32 + nn;
            float v = h3[n * 32 + lane] * w3r;
#pragma unroll
            for (int off = 16; off; off >>= 1)
                v += __shfl_xor_sync(0xffffffffu, v, off);
            if (lane == 0) g1[n] = v;
        }
        __syncthreads();
        {
            float acc = g1[t];
            int beg = offs[t], end = offs[t + 1];
            for (int j = beg; j < end; j += 4) {
                int4 e4 = *(const int4*)(elist + j);
                acc += (g1[e4.x >> 5] + g1[e4.y >> 5])
                     + (g1[e4.z >> 5] + g1[e4.w >> 5]);
            }
            z4[t] = tanhf((acc + b3v) * invd[t]);
        }
        __syncthreads();
    }

    // ---- sortpool: rank = #{j : v_j > v_i or (==, j<i)}, keep top-30 ----
    int* selrow = cnt;
    {
        float v = z4[t];
        int r = 0;
#pragma unroll 4
        for (int j0 = 0; j0 < 256; j0 += 4) {
            float4 u4 = *(const float4*)(z4 + j0);
            r += (int)((u4.x > v) || (u4.x == v && (j0    ) < t));
            r += (int)((u4.y > v) || (u4.y == v && (j0 + 1) < t));
            r += (int)((u4.z > v) || (u4.z == v && (j0 + 2) < t));
            r += (int)((u4.w > v) || (u4.w == v && (j0 + 3) < t));
        }
        if (r < KTOP) selrow[r] = t;
    }
    __syncthreads();

    // ---- gather sp[30][97] ----
    float* sp = scr;   // g1 dead now
    for (int i = t; i < KTOP * DLAT; i += NT) {
        int k = i / DLAT, d = i - k * DLAT;
        int n = selrow[k];
        float v;
        if (d < 32)      v = h1[n * 32 + d];
        else if (d < 64) v = h2[n * 32 + d - 32];
        else if (d < 96) v = h3[n * 32 + d - 64];
        else             v = z4[n];
        sp[i] = v;
    }
    __syncthreads();

    // ---- conv1 (stride D) + relu -> out1[16][30] ----
    float* out1 = scr + 3000;
    for (int i = t; i < C1_ * KTOP; i += NT) {
        int c = i & 15, k = i >> 4;
        float acc = c1b[c];
        const float* wr = c1w + c * DLAT;
        const float* sr = sp + k * DLAT;
        for (int d = 0; d < DLAT; d++) acc = fmaf(sr[d], wr[d], acc);
        out1[c * KTOP + k] = fmaxf(acc, 0.f);
    }
    __syncthreads();

    // ---- maxpool(2,2) -> pool[16][15] ----
    float* pool = scr + 3500;
    if (t < C1_ * 15) {
        int c = t / 15, tt = t - c * 15;
        pool[t] = fmaxf(out1[c * KTOP + 2 * tt], out1[c * KTOP + 2 * tt + 1]);
    }
    __syncthreads();

    // ---- conv2 (kw=5) + relu -> out2[32][11]  (352 outputs -> strided loop!) ----
    float* out2 = scr + 3800;
    for (int i = t; i < C2_ * T2_; i += NT) {
        int c2 = i / T2_, tt = i - c2 * T2_;
        float acc = c2b[c2];
#pragma unroll
        for (int c1 = 0; c1 < C1_; c1++) {
            const float* wv = c2w + (c2 * C1_ + c1) * 5;
            const float* pv = pool + c1 * 15 + tt;
#pragma unroll
            for (int j = 0; j < 5; j++) acc = fmaf(pv[j], wv[j], acc);
        }
        out2[i] = fmaxf(acc, 0.f);
    }
    __syncthreads();

    // ---- dense [352]x[352,2] + relu ----
    if (w == 0) {
        float a0 = 0.f, a1 = 0.f;
        for (int i = lane; i < DENSE_; i += 32) {
            float x = out2[i];
            a0 = fmaf(x, ow[i * 2 + 0], a0);
            a1 = fmaf(x, ow[i * 2 + 1], a1);
        }
#pragma unroll
        for (int off = 16; off; off >>= 1) {
            a0 += __shfl_xor_sync(0xffffffffu, a0, off);
            a1 += __shfl_xor_sync(0xffffffffu, a1, off);
        }
        if (lane == 0) {
            out[b * 2 + 0] = fmaxf(a0 + ob[0], 0.f);
            out[b * 2 + 1] = fmaxf(a1 + ob[1], 0.f);
        }
    }
}

extern "C" void kernel_launch(void* const* d_in, const int* in_sizes, int n_in,
                              void* d_out, int out_size)
{
    int iSrc, iDst, iDeg, iW0, ib0, iW1, ib1, iW2, ib2, iW3, ib3;
    int ic1w, ic1b, ic2w, ic2b, iow, iob;
    if (n_in > 1 && in_sizes[1] == NGR * EPG) {
        iSrc = 1; iDst = 2; iDeg = 3;
        iW0 = 4;  ib0 = 5;  iW1 = 6;  ib1 = 7;
        iW2 = 8;  ib2 = 9;  iW3 = 10; ib3 = 11;
        ic1w = 12; ic1b = 13; ic2w = 14; ic2b = 15; iow = 16; iob = 17;
    } else {
        iW0 = 1;  ib0 = 2;  iW1 = 3;  ib1 = 4;
        iW2 = 5;  ib2 = 6;  iW3 = 7;  ib3 = 8;
        ic1w = 9; ic1b = 10; ic2w = 11; ic2b = 12; iow = 13; iob = 14;
        iSrc = 15; iDst = 16; iDeg = 17;
    }

    cudaFuncSetAttribute(dgcnn_kernel,
                         cudaFuncAttributeMaxDynamicSharedMemorySize, SMEM_BYTES);

    dgcnn_kernel<<<NGR, NT, SMEM_BYTES>>>(
        (const float*)d_in[0],
        (const int*)d_in[iSrc], (const int*)d_in[iDst], (const int*)d_in[iDeg],
        (const float*)d_in[iW0], (const float*)d_in[ib0],
        (const float*)d_in[iW1], (const float*)d_in[ib1],
        (const float*)d_in[iW2], (const float*)d_in[ib2],
        (const float*)d_in[iW3], (const float*)d_in[ib3],
        (const float*)d_in[ic1w], (const float*)d_in[ic1b],
        (const float*)d_in[ic2w], (const float*)d_in[ic2b],
        (const float*)d_in[iow], (const float*)d_in[iob],
        (float*)d_out);
}